// round 4
// baseline (speedup 1.0000x reference)
#include <cuda_runtime.h>
#include <cuda_fp16.h>
#include <cuda_bf16.h>

#define NODE_SIZE 100000
#define DIM 128

// fp16 copy of z (25.6 MB scratch; __device__ globals are the sanctioned scratch)
__device__ __half g_z16[NODE_SIZE * DIM];

// Folded weights: logit(e) = sum_d relu(zi[d])*v[d] + relu(zj[d])*v[128+d]
//                          + zi[d]*zj[d]*w3b[d]
__device__ float g_v[256];
__device__ float g_w3b[128];

__global__ void precompute_kernel(const float* __restrict__ W2,
                                  const float* __restrict__ W3) {
    int k = threadIdx.x;  // 256 threads
    if (k < 256) {
        float s = 0.f;
        const float* row = W2 + k * 128;
        #pragma unroll 4
        for (int d = 0; d < 128; ++d) s = fmaf(row[d], W3[d], s);
        g_v[k] = s;
    }
    if (k < 128) g_w3b[k] = W3[128 + k];
}

// Convert z (fp32) -> g_z16 (fp16). 3.2M float4 -> 3.2M uint2.
__global__ __launch_bounds__(256) void convert_kernel(const float* __restrict__ z) {
    const int n4 = NODE_SIZE * DIM / 4;  // 3.2M
    const float4* __restrict__ src = reinterpret_cast<const float4*>(z);
    uint2* __restrict__ dst = reinterpret_cast<uint2*>(g_z16);
    int i = blockIdx.x * blockDim.x + threadIdx.x;
    int stride = gridDim.x * blockDim.x;
    for (; i < n4; i += stride) {
        float4 f = __ldg(src + i);
        __half2 h0 = __floats2half2_rn(f.x, f.y);
        __half2 h1 = __floats2half2_rn(f.z, f.w);
        uint2 u;
        u.x = *reinterpret_cast<unsigned*>(&h0);
        u.y = *reinterpret_cast<unsigned*>(&h1);
        dst[i] = u;
    }
}

__device__ __forceinline__ float edge_partial_h(const uint2 ua, const uint2 ub,
                                                const float4 va, const float4 vb,
                                                const float4 w) {
    __half2 a01 = *reinterpret_cast<const __half2*>(&ua.x);
    __half2 a23 = *reinterpret_cast<const __half2*>(&ua.y);
    __half2 b01 = *reinterpret_cast<const __half2*>(&ub.x);
    __half2 b23 = *reinterpret_cast<const __half2*>(&ub.y);
    float2 fa0 = __half22float2(a01), fa1 = __half22float2(a23);
    float2 fb0 = __half22float2(b01), fb1 = __half22float2(b23);
    float s = 0.f;
    s = fmaf(fmaxf(fa0.x, 0.f), va.x, s);
    s = fmaf(fmaxf(fa0.y, 0.f), va.y, s);
    s = fmaf(fmaxf(fa1.x, 0.f), va.z, s);
    s = fmaf(fmaxf(fa1.y, 0.f), va.w, s);
    s = fmaf(fmaxf(fb0.x, 0.f), vb.x, s);
    s = fmaf(fmaxf(fb0.y, 0.f), vb.y, s);
    s = fmaf(fmaxf(fb1.x, 0.f), vb.z, s);
    s = fmaf(fmaxf(fb1.y, 0.f), vb.w, s);
    s = fmaf(fa0.x * fb0.x, w.x, s);
    s = fmaf(fa0.y * fb0.y, w.y, s);
    s = fmaf(fa1.x * fb1.x, w.z, s);
    s = fmaf(fa1.y * fb1.y, w.w, s);
    return s;
}

// Reduce 4 warp-wide accumulators with 9 SHFL + 3 SEL.
// Result: lane0 -> sum(s0), lane16 -> sum(s1), lane8 -> sum(s2), lane24 -> sum(s3).
__device__ __forceinline__ float reduce4(float s0, float s1, float s2, float s3,
                                         int lane) {
    s0 += __shfl_xor_sync(0xFFFFFFFFu, s0, 16);
    s1 += __shfl_xor_sync(0xFFFFFFFFu, s1, 16);
    s2 += __shfl_xor_sync(0xFFFFFFFFu, s2, 16);
    s3 += __shfl_xor_sync(0xFFFFFFFFu, s3, 16);
    float c01 = (lane & 16) ? s1 : s0;
    float c23 = (lane & 16) ? s3 : s2;
    c01 += __shfl_xor_sync(0xFFFFFFFFu, c01, 8);
    c23 += __shfl_xor_sync(0xFFFFFFFFu, c23, 8);
    float d = (lane & 8) ? c23 : c01;
    d += __shfl_xor_sync(0xFFFFFFFFu, d, 4);
    d += __shfl_xor_sync(0xFFFFFFFFu, d, 2);
    d += __shfl_xor_sync(0xFFFFFFFFu, d, 1);
    return d;
}

__global__ __launch_bounds__(256, 3) void neumf_kernel(
    const int* __restrict__ e_true,
    const int* __restrict__ e_false,
    float* __restrict__ out,
    int E_true, int E_total)
{
    const int lane   = threadIdx.x & 31;
    const int warp   = (blockIdx.x * blockDim.x + threadIdx.x) >> 5;
    const int nwarps = (gridDim.x * blockDim.x) >> 5;

    const float4 va = *reinterpret_cast<const float4*>(&g_v[lane * 4]);
    const float4 vb = *reinterpret_cast<const float4*>(&g_v[128 + lane * 4]);
    const float4 w  = *reinterpret_cast<const float4*>(&g_w3b[lane * 4]);

    // row gather: 32 lanes x 8B (4 halves) = 256B/row
    const uint2* __restrict__ zr = reinterpret_cast<const uint2*>(g_z16);

    int e = warp * 8;
    const int stride = nwarps * 8;

    for (; e + 7 < E_total; e += stride) {
        // --- indices: 4 uniform int4 loads when group doesn't straddle ---
        int2 id[8];
        if (e + 8 <= E_true) {
            const int4* p = reinterpret_cast<const int4*>(e_true + 2 * e);
            int4 q0 = __ldg(p + 0), q1 = __ldg(p + 1);
            int4 q2 = __ldg(p + 2), q3 = __ldg(p + 3);
            id[0] = make_int2(q0.x, q0.y); id[1] = make_int2(q0.z, q0.w);
            id[2] = make_int2(q1.x, q1.y); id[3] = make_int2(q1.z, q1.w);
            id[4] = make_int2(q2.x, q2.y); id[5] = make_int2(q2.z, q2.w);
            id[6] = make_int2(q3.x, q3.y); id[7] = make_int2(q3.z, q3.w);
        } else if (e >= E_true) {
            const int4* p = reinterpret_cast<const int4*>(e_false + 2 * (e - E_true));
            int4 q0 = __ldg(p + 0), q1 = __ldg(p + 1);
            int4 q2 = __ldg(p + 2), q3 = __ldg(p + 3);
            id[0] = make_int2(q0.x, q0.y); id[1] = make_int2(q0.z, q0.w);
            id[2] = make_int2(q1.x, q1.y); id[3] = make_int2(q1.z, q1.w);
            id[4] = make_int2(q2.x, q2.y); id[5] = make_int2(q2.z, q2.w);
            id[6] = make_int2(q3.x, q3.y); id[7] = make_int2(q3.z, q3.w);
        } else {
            #pragma unroll
            for (int k = 0; k < 8; ++k) {
                int ek = e + k;
                id[k] = __ldg(reinterpret_cast<const int2*>(
                    ek < E_true ? e_true + 2 * ek
                                : e_false + 2 * (ek - E_true)));
            }
        }

        // --- 16 row gathers (LDG.64), all issued before any consume ---
        uint2 a[8], b[8];
        #pragma unroll
        for (int k = 0; k < 8; ++k) {
            a[k] = __ldg(zr + (((size_t)id[k].x << 5) + lane));
            b[k] = __ldg(zr + (((size_t)id[k].y << 5) + lane));
        }

        float s[8];
        #pragma unroll
        for (int k = 0; k < 8; ++k)
            s[k] = edge_partial_h(a[k], b[k], va, vb, w);

        float d0 = reduce4(s[0], s[1], s[2], s[3], lane);
        float d1 = reduce4(s[4], s[5], s[6], s[7], lane);

        if ((lane & 7) == 0) {
            int off = ((lane >> 3) & 1) * 2 + (lane >> 4);  // 0->0, 8->2, 16->1, 24->3
            out[e + off]     = 1.f / (1.f + __expf(-d0));
            out[e + 4 + off] = 1.f / (1.f + __expf(-d1));
        }
    }

    // Tail
    for (; e < E_total; ++e) {
        int2 i0 = __ldg(reinterpret_cast<const int2*>(
             e < E_true ? e_true + 2 * e : e_false + 2 * (e - E_true)));
        const uint2 aa = __ldg(zr + (((size_t)i0.x << 5) + lane));
        const uint2 bb = __ldg(zr + (((size_t)i0.y << 5) + lane));
        float s = edge_partial_h(aa, bb, va, vb, w);
        #pragma unroll
        for (int off = 16; off; off >>= 1)
            s += __shfl_xor_sync(0xFFFFFFFFu, s, off);
        if (lane == 0)
            out[e] = 1.f / (1.f + __expf(-s));
    }
}

extern "C" void kernel_launch(void* const* d_in, const int* in_sizes, int n_in,
                              void* d_out, int out_size) {
    // metadata order: X, train_edges, train_false_edges, z, weight_two, weight_three
    const int*   e_true  = (const int*)  d_in[1];
    const int*   e_false = (const int*)  d_in[2];
    const float* z       = (const float*)d_in[3];
    const float* W2      = (const float*)d_in[4];
    const float* W3      = (const float*)d_in[5];
    float* out = (float*)d_out;

    const int E_true  = in_sizes[1] / 2;
    const int E_total = E_true + in_sizes[2] / 2;

    precompute_kernel<<<1, 256>>>(W2, W3);

    int sm_count = 148;
    cudaDeviceGetAttribute(&sm_count, cudaDevAttrMultiProcessorCount, 0);

    convert_kernel<<<sm_count * 8, 256>>>(z);

    int blocks_per_sm = 3;
    cudaOccupancyMaxActiveBlocksPerMultiprocessor(&blocks_per_sm, neumf_kernel, 256, 0);
    if (blocks_per_sm < 1) blocks_per_sm = 1;

    neumf_kernel<<<sm_count * blocks_per_sm, 256>>>(e_true, e_false, out,
                                                    E_true, E_total);
}

// round 5
// speedup vs baseline: 1.1647x; 1.1647x over previous
#include <cuda_runtime.h>
#include <cuda_fp16.h>
#include <cuda_fp8.h>
#include <cuda_bf16.h>

#define NODE_SIZE 100000
#define DIM 128

// fp8 copy of z*256 (12.8 MB scratch; __device__ globals are the sanctioned scratch)
__device__ unsigned char g_z8[NODE_SIZE * DIM];

// Folded weights (with fp8 scaling folded in):
//   logit(e) = sum_d relu(z8i[d])*v[d] + relu(z8j[d])*v[128+d] + z8i*z8j*w3b[d]
//   g_v[k]   = (sum_d W2[k,d]*W3[d]) * 2^-8
//   g_w3b[d] = W3[128+d] * 2^-16
__device__ float g_v[256];
__device__ float g_w3b[128];

__global__ void precompute_kernel(const float* __restrict__ W2,
                                  const float* __restrict__ W3) {
    int k = threadIdx.x;  // 256 threads
    if (k < 256) {
        const float4* row = reinterpret_cast<const float4*>(W2 + k * 128);
        const float4* w3  = reinterpret_cast<const float4*>(W3);
        float s = 0.f;
        #pragma unroll
        for (int d = 0; d < 32; ++d) {
            float4 r = __ldg(row + d);
            float4 t = __ldg(w3 + d);
            s = fmaf(r.x, t.x, s);
            s = fmaf(r.y, t.y, s);
            s = fmaf(r.z, t.z, s);
            s = fmaf(r.w, t.w, s);
        }
        g_v[k] = s * 0.00390625f;  // 2^-8
    }
    if (k < 128) g_w3b[k] = W3[128 + k] * 1.52587890625e-05f;  // 2^-16
}

// Convert z (fp32) -> g_z8 = e4m3(z * 256). Each thread: 4 float4 in, 1 uint4 out.
__global__ __launch_bounds__(256) void convert_kernel(const float* __restrict__ z) {
    const int n16 = NODE_SIZE * DIM / 16;  // 800K groups of 16 elements
    const float4* __restrict__ src = reinterpret_cast<const float4*>(z);
    uint4* __restrict__ dst = reinterpret_cast<uint4*>(g_z8);
    int i = blockIdx.x * blockDim.x + threadIdx.x;
    int stride = gridDim.x * blockDim.x;
    for (; i < n16; i += stride) {
        uint4 u;
        unsigned* up = &u.x;
        #pragma unroll
        for (int q = 0; q < 4; ++q) {
            float4 f = __ldg(src + i * 4 + q);
            float2 lo = make_float2(f.x * 256.f, f.y * 256.f);
            float2 hi = make_float2(f.z * 256.f, f.w * 256.f);
            unsigned short plo = __nv_cvt_float2_to_fp8x2(lo, __NV_SATFINITE, __NV_E4M3);
            unsigned short phi = __nv_cvt_float2_to_fp8x2(hi, __NV_SATFINITE, __NV_E4M3);
            up[q] = (unsigned)plo | ((unsigned)phi << 16);
        }
        dst[i] = u;
    }
}

__device__ __forceinline__ float2 fp8x2_to_float2(unsigned short v) {
    __half2_raw hr = __nv_cvt_fp8x2_to_halfraw2((__nv_fp8x2_storage_t)v, __NV_E4M3);
    __half2 h = *reinterpret_cast<__half2*>(&hr);
    return __half22float2(h);
}

__device__ __forceinline__ float edge_partial8(const unsigned ua, const unsigned ub,
                                               const float4 va, const float4 vb,
                                               const float4 w) {
    float2 fa0 = fp8x2_to_float2((unsigned short)(ua & 0xFFFF));
    float2 fa1 = fp8x2_to_float2((unsigned short)(ua >> 16));
    float2 fb0 = fp8x2_to_float2((unsigned short)(ub & 0xFFFF));
    float2 fb1 = fp8x2_to_float2((unsigned short)(ub >> 16));
    float s = 0.f;
    s = fmaf(fmaxf(fa0.x, 0.f), va.x, s);
    s = fmaf(fmaxf(fa0.y, 0.f), va.y, s);
    s = fmaf(fmaxf(fa1.x, 0.f), va.z, s);
    s = fmaf(fmaxf(fa1.y, 0.f), va.w, s);
    s = fmaf(fmaxf(fb0.x, 0.f), vb.x, s);
    s = fmaf(fmaxf(fb0.y, 0.f), vb.y, s);
    s = fmaf(fmaxf(fb1.x, 0.f), vb.z, s);
    s = fmaf(fmaxf(fb1.y, 0.f), vb.w, s);
    s = fmaf(fa0.x * fb0.x, w.x, s);
    s = fmaf(fa0.y * fb0.y, w.y, s);
    s = fmaf(fa1.x * fb1.x, w.z, s);
    s = fmaf(fa1.y * fb1.y, w.w, s);
    return s;
}

// Reduce 4 warp-wide accumulators with 9 SHFL + 3 SEL.
// Result: lane0 -> sum(s0), lane16 -> sum(s1), lane8 -> sum(s2), lane24 -> sum(s3).
__device__ __forceinline__ float reduce4(float s0, float s1, float s2, float s3,
                                         int lane) {
    s0 += __shfl_xor_sync(0xFFFFFFFFu, s0, 16);
    s1 += __shfl_xor_sync(0xFFFFFFFFu, s1, 16);
    s2 += __shfl_xor_sync(0xFFFFFFFFu, s2, 16);
    s3 += __shfl_xor_sync(0xFFFFFFFFu, s3, 16);
    float c01 = (lane & 16) ? s1 : s0;
    float c23 = (lane & 16) ? s3 : s2;
    c01 += __shfl_xor_sync(0xFFFFFFFFu, c01, 8);
    c23 += __shfl_xor_sync(0xFFFFFFFFu, c23, 8);
    float d = (lane & 8) ? c23 : c01;
    d += __shfl_xor_sync(0xFFFFFFFFu, d, 4);
    d += __shfl_xor_sync(0xFFFFFFFFu, d, 2);
    d += __shfl_xor_sync(0xFFFFFFFFu, d, 1);
    return d;
}

__global__ __launch_bounds__(256, 3) void neumf_kernel(
    const int* __restrict__ e_true,
    const int* __restrict__ e_false,
    float* __restrict__ out,
    int E_true, int E_total)
{
    const int lane   = threadIdx.x & 31;
    const int warp   = (blockIdx.x * blockDim.x + threadIdx.x) >> 5;
    const int nwarps = (gridDim.x * blockDim.x) >> 5;

    const float4 va = *reinterpret_cast<const float4*>(&g_v[lane * 4]);
    const float4 vb = *reinterpret_cast<const float4*>(&g_v[128 + lane * 4]);
    const float4 w  = *reinterpret_cast<const float4*>(&g_w3b[lane * 4]);

    // row gather: 32 lanes x 4B (4 fp8) = 128B/row = 1 L1 wavefront
    const unsigned* __restrict__ zr = reinterpret_cast<const unsigned*>(g_z8);

    int e = warp * 8;
    const int stride = nwarps * 8;

    for (; e + 7 < E_total; e += stride) {
        // --- indices: 4 uniform int4 loads when group doesn't straddle ---
        int2 id[8];
        if (e + 8 <= E_true) {
            const int4* p = reinterpret_cast<const int4*>(e_true + 2 * e);
            int4 q0 = __ldg(p + 0), q1 = __ldg(p + 1);
            int4 q2 = __ldg(p + 2), q3 = __ldg(p + 3);
            id[0] = make_int2(q0.x, q0.y); id[1] = make_int2(q0.z, q0.w);
            id[2] = make_int2(q1.x, q1.y); id[3] = make_int2(q1.z, q1.w);
            id[4] = make_int2(q2.x, q2.y); id[5] = make_int2(q2.z, q2.w);
            id[6] = make_int2(q3.x, q3.y); id[7] = make_int2(q3.z, q3.w);
        } else if (e >= E_true) {
            const int4* p = reinterpret_cast<const int4*>(e_false + 2 * (e - E_true));
            int4 q0 = __ldg(p + 0), q1 = __ldg(p + 1);
            int4 q2 = __ldg(p + 2), q3 = __ldg(p + 3);
            id[0] = make_int2(q0.x, q0.y); id[1] = make_int2(q0.z, q0.w);
            id[2] = make_int2(q1.x, q1.y); id[3] = make_int2(q1.z, q1.w);
            id[4] = make_int2(q2.x, q2.y); id[5] = make_int2(q2.z, q2.w);
            id[6] = make_int2(q3.x, q3.y); id[7] = make_int2(q3.z, q3.w);
        } else {
            #pragma unroll
            for (int k = 0; k < 8; ++k) {
                int ek = e + k;
                id[k] = __ldg(reinterpret_cast<const int2*>(
                    ek < E_true ? e_true + 2 * ek
                                : e_false + 2 * (ek - E_true)));
            }
        }

        // --- 16 row gathers (LDG.32), all issued before any consume ---
        unsigned a[8], b[8];
        #pragma unroll
        for (int k = 0; k < 8; ++k) {
            a[k] = __ldg(zr + (((size_t)id[k].x << 5) + lane));
            b[k] = __ldg(zr + (((size_t)id[k].y << 5) + lane));
        }

        float s[8];
        #pragma unroll
        for (int k = 0; k < 8; ++k)
            s[k] = edge_partial8(a[k], b[k], va, vb, w);

        float d0 = reduce4(s[0], s[1], s[2], s[3], lane);
        float d1 = reduce4(s[4], s[5], s[6], s[7], lane);

        if ((lane & 7) == 0) {
            int off = ((lane >> 3) & 1) * 2 + (lane >> 4);  // 0->0, 8->2, 16->1, 24->3
            out[e + off]     = 1.f / (1.f + __expf(-d0));
            out[e + 4 + off] = 1.f / (1.f + __expf(-d1));
        }
    }

    // Tail
    for (; e < E_total; ++e) {
        int2 i0 = __ldg(reinterpret_cast<const int2*>(
             e < E_true ? e_true + 2 * e : e_false + 2 * (e - E_true)));
        const unsigned aa = __ldg(zr + (((size_t)i0.x << 5) + lane));
        const unsigned bb = __ldg(zr + (((size_t)i0.y << 5) + lane));
        float s = edge_partial8(aa, bb, va, vb, w);
        #pragma unroll
        for (int off = 16; off; off >>= 1)
            s += __shfl_xor_sync(0xFFFFFFFFu, s, off);
        if (lane == 0)
            out[e] = 1.f / (1.f + __expf(-s));
    }
}

extern "C" void kernel_launch(void* const* d_in, const int* in_sizes, int n_in,
                              void* d_out, int out_size) {
    // metadata order: X, train_edges, train_false_edges, z, weight_two, weight_three
    const int*   e_true  = (const int*)  d_in[1];
    const int*   e_false = (const int*)  d_in[2];
    const float* z       = (const float*)d_in[3];
    const float* W2      = (const float*)d_in[4];
    const float* W3      = (const float*)d_in[5];
    float* out = (float*)d_out;

    const int E_true  = in_sizes[1] / 2;
    const int E_total = E_true + in_sizes[2] / 2;

    precompute_kernel<<<1, 256>>>(W2, W3);

    int sm_count = 148;
    cudaDeviceGetAttribute(&sm_count, cudaDevAttrMultiProcessorCount, 0);

    convert_kernel<<<sm_count * 8, 256>>>(z);

    int blocks_per_sm = 3;
    cudaOccupancyMaxActiveBlocksPerMultiprocessor(&blocks_per_sm, neumf_kernel, 256, 0);
    if (blocks_per_sm < 1) blocks_per_sm = 1;

    neumf_kernel<<<sm_count * blocks_per_sm, 256>>>(e_true, e_false, out,
                                                    E_true, E_total);
}

// round 6
// speedup vs baseline: 1.4847x; 1.2748x over previous
#include <cuda_runtime.h>
#include <cuda_fp16.h>
#include <cuda_fp8.h>
#include <cuda_bf16.h>

#define NODE_SIZE 100000
#define DIM 128

// fp8 copy of z*256 (12.8 MB scratch)
__device__ unsigned char g_z8[NODE_SIZE * DIM];

// Unscaled folded weights (scales 2^-8 / 2^-16 applied in main kernel):
//   g_v[k]   = sum_d W2[k,d]*W3[d]
//   g_w3b[d] = W3[128+d]
__device__ float g_v[256];
__device__ float g_w3b[128];

// Convert z (fp32) -> g_z8 = e4m3(z * 256), AND fold weights (first 256 warps).
__global__ __launch_bounds__(256) void convert_kernel(const float* __restrict__ z,
                                                      const float* __restrict__ W2,
                                                      const float* __restrict__ W3) {
    const int tid    = blockIdx.x * blockDim.x + threadIdx.x;
    const int gwarp  = tid >> 5;
    const int lane   = threadIdx.x & 31;

    // --- weight fold: warp gwarp computes g_v[gwarp] ---
    if (gwarp < 256) {
        float4 r = __ldg(reinterpret_cast<const float4*>(W2 + gwarp * 128) + lane);
        float4 t = __ldg(reinterpret_cast<const float4*>(W3) + lane);
        float s = r.x * t.x;
        s = fmaf(r.y, t.y, s);
        s = fmaf(r.z, t.z, s);
        s = fmaf(r.w, t.w, s);
        #pragma unroll
        for (int off = 16; off; off >>= 1)
            s += __shfl_xor_sync(0xFFFFFFFFu, s, off);
        if (lane == 0) g_v[gwarp] = s;
    }
    if (blockIdx.x == 0 && threadIdx.x < 128)
        g_w3b[threadIdx.x] = __ldg(W3 + 128 + threadIdx.x);

    // --- conversion: grid-stride over 800K groups of 16 elements ---
    const int n16 = NODE_SIZE * DIM / 16;
    const float4* __restrict__ src = reinterpret_cast<const float4*>(z);
    uint4* __restrict__ dst = reinterpret_cast<uint4*>(g_z8);
    const int stride = gridDim.x * blockDim.x;
    for (int i = tid; i < n16; i += stride) {
        uint4 u;
        unsigned* up = &u.x;
        #pragma unroll
        for (int q = 0; q < 4; ++q) {
            float4 f = __ldg(src + i * 4 + q);
            float2 lo = make_float2(f.x * 256.f, f.y * 256.f);
            float2 hi = make_float2(f.z * 256.f, f.w * 256.f);
            unsigned short plo = __nv_cvt_float2_to_fp8x2(lo, __NV_SATFINITE, __NV_E4M3);
            unsigned short phi = __nv_cvt_float2_to_fp8x2(hi, __NV_SATFINITE, __NV_E4M3);
            up[q] = (unsigned)plo | ((unsigned)phi << 16);
        }
        dst[i] = u;
    }
}

__device__ __forceinline__ __half2 fp8x2_to_half2(unsigned short v) {
    __half2_raw hr = __nv_cvt_fp8x2_to_halfraw2((__nv_fp8x2_storage_t)v, __NV_E4M3);
    return *reinterpret_cast<__half2*>(&hr);
}

// Packed-half2 edge partial. Two accumulators keep operands in normal half range;
// 2^-8 (relu path) and 2^-16 (product path) applied at float finalize.
__device__ __forceinline__ float edge_partial8h(unsigned ua, unsigned ub,
                                                __half2 va0, __half2 va1,
                                                __half2 vb0, __half2 vb1,
                                                __half2 w0, __half2 w1,
                                                __half2 hz) {
    __half2 a01 = fp8x2_to_half2((unsigned short)(ua & 0xFFFF));
    __half2 a23 = fp8x2_to_half2((unsigned short)(ua >> 16));
    __half2 b01 = fp8x2_to_half2((unsigned short)(ub & 0xFFFF));
    __half2 b23 = fp8x2_to_half2((unsigned short)(ub >> 16));

    __half2 acc1 = __hmul2(__hmax2(a01, hz), va0);
    acc1 = __hfma2(__hmax2(a23, hz), va1, acc1);
    acc1 = __hfma2(__hmax2(b01, hz), vb0, acc1);
    acc1 = __hfma2(__hmax2(b23, hz), vb1, acc1);

    __half2 acc2 = __hmul2(__hmul2(a01, b01), w0);
    acc2 = __hfma2(__hmul2(a23, b23), w1, acc2);

    float2 f1 = __half22float2(acc1);
    float2 f2 = __half22float2(acc2);
    return (f1.x + f1.y) * 0x1p-8f + (f2.x + f2.y) * 0x1p-16f;
}

// Reduce 4 warp-wide accumulators with 9 SHFL + 3 SEL.
// Result: lane0 -> sum(s0), lane16 -> sum(s1), lane8 -> sum(s2), lane24 -> sum(s3).
__device__ __forceinline__ float reduce4(float s0, float s1, float s2, float s3,
                                         int lane) {
    s0 += __shfl_xor_sync(0xFFFFFFFFu, s0, 16);
    s1 += __shfl_xor_sync(0xFFFFFFFFu, s1, 16);
    s2 += __shfl_xor_sync(0xFFFFFFFFu, s2, 16);
    s3 += __shfl_xor_sync(0xFFFFFFFFu, s3, 16);
    float c01 = (lane & 16) ? s1 : s0;
    float c23 = (lane & 16) ? s3 : s2;
    c01 += __shfl_xor_sync(0xFFFFFFFFu, c01, 8);
    c23 += __shfl_xor_sync(0xFFFFFFFFu, c23, 8);
    float d = (lane & 8) ? c23 : c01;
    d += __shfl_xor_sync(0xFFFFFFFFu, d, 4);
    d += __shfl_xor_sync(0xFFFFFFFFu, d, 2);
    d += __shfl_xor_sync(0xFFFFFFFFu, d, 1);
    return d;
}

__global__ __launch_bounds__(256, 3) void neumf_kernel(
    const int* __restrict__ e_true,
    const int* __restrict__ e_false,
    float* __restrict__ out,
    int E_true, int E_total)
{
    const int lane   = threadIdx.x & 31;
    const int warp   = (blockIdx.x * blockDim.x + threadIdx.x) >> 5;
    const int nwarps = (gridDim.x * blockDim.x) >> 5;

    // Per-lane weights -> half2 (one-time cost per warp)
    const float4 vaf = *reinterpret_cast<const float4*>(&g_v[lane * 4]);
    const float4 vbf = *reinterpret_cast<const float4*>(&g_v[128 + lane * 4]);
    const float4 wf  = *reinterpret_cast<const float4*>(&g_w3b[lane * 4]);
    const __half2 va0 = __floats2half2_rn(vaf.x, vaf.y);
    const __half2 va1 = __floats2half2_rn(vaf.z, vaf.w);
    const __half2 vb0 = __floats2half2_rn(vbf.x, vbf.y);
    const __half2 vb1 = __floats2half2_rn(vbf.z, vbf.w);
    const __half2 w0  = __floats2half2_rn(wf.x, wf.y);
    const __half2 w1  = __floats2half2_rn(wf.z, wf.w);
    const __half2 hz  = __float2half2_rn(0.f);

    // row gather: 32 lanes x 4B (4 fp8) = 128B/row = 1 L1 wavefront
    const unsigned* __restrict__ zr = reinterpret_cast<const unsigned*>(g_z8);

    int e = warp * 8;
    const int stride = nwarps * 8;

    for (; e + 7 < E_total; e += stride) {
        // --- indices: 4 uniform int4 loads when group doesn't straddle ---
        int2 id[8];
        if (e + 8 <= E_true) {
            const int4* p = reinterpret_cast<const int4*>(e_true + 2 * e);
            int4 q0 = __ldg(p + 0), q1 = __ldg(p + 1);
            int4 q2 = __ldg(p + 2), q3 = __ldg(p + 3);
            id[0] = make_int2(q0.x, q0.y); id[1] = make_int2(q0.z, q0.w);
            id[2] = make_int2(q1.x, q1.y); id[3] = make_int2(q1.z, q1.w);
            id[4] = make_int2(q2.x, q2.y); id[5] = make_int2(q2.z, q2.w);
            id[6] = make_int2(q3.x, q3.y); id[7] = make_int2(q3.z, q3.w);
        } else if (e >= E_true) {
            const int4* p = reinterpret_cast<const int4*>(e_false + 2 * (e - E_true));
            int4 q0 = __ldg(p + 0), q1 = __ldg(p + 1);
            int4 q2 = __ldg(p + 2), q3 = __ldg(p + 3);
            id[0] = make_int2(q0.x, q0.y); id[1] = make_int2(q0.z, q0.w);
            id[2] = make_int2(q1.x, q1.y); id[3] = make_int2(q1.z, q1.w);
            id[4] = make_int2(q2.x, q2.y); id[5] = make_int2(q2.z, q2.w);
            id[6] = make_int2(q3.x, q3.y); id[7] = make_int2(q3.z, q3.w);
        } else {
            #pragma unroll
            for (int k = 0; k < 8; ++k) {
                int ek = e + k;
                id[k] = __ldg(reinterpret_cast<const int2*>(
                    ek < E_true ? e_true + 2 * ek
                                : e_false + 2 * (ek - E_true)));
            }
        }

        // --- 16 row gathers (LDG.32), all issued before any consume ---
        unsigned a[8], b[8];
        #pragma unroll
        for (int k = 0; k < 8; ++k) {
            a[k] = __ldg(zr + (((size_t)id[k].x << 5) + lane));
            b[k] = __ldg(zr + (((size_t)id[k].y << 5) + lane));
        }

        float s[8];
        #pragma unroll
        for (int k = 0; k < 8; ++k)
            s[k] = edge_partial8h(a[k], b[k], va0, va1, vb0, vb1, w0, w1, hz);

        float d0 = reduce4(s[0], s[1], s[2], s[3], lane);
        float d1 = reduce4(s[4], s[5], s[6], s[7], lane);

        if ((lane & 7) == 0) {
            int off = ((lane >> 3) & 1) * 2 + (lane >> 4);  // 0->0, 8->2, 16->1, 24->3
            out[e + off]     = 1.f / (1.f + __expf(-d0));
            out[e + 4 + off] = 1.f / (1.f + __expf(-d1));
        }
    }

    // Tail
    for (; e < E_total; ++e) {
        int2 i0 = __ldg(reinterpret_cast<const int2*>(
             e < E_true ? e_true + 2 * e : e_false + 2 * (e - E_true)));
        const unsigned aa = __ldg(zr + (((size_t)i0.x << 5) + lane));
        const unsigned bb = __ldg(zr + (((size_t)i0.y << 5) + lane));
        float s = edge_partial8h(aa, bb, va0, va1, vb0, vb1, w0, w1, hz);
        #pragma unroll
        for (int off = 16; off; off >>= 1)
            s += __shfl_xor_sync(0xFFFFFFFFu, s, off);
        if (lane == 0)
            out[e] = 1.f / (1.f + __expf(-s));
    }
}

extern "C" void kernel_launch(void* const* d_in, const int* in_sizes, int n_in,
                              void* d_out, int out_size) {
    // metadata order: X, train_edges, train_false_edges, z, weight_two, weight_three
    const int*   e_true  = (const int*)  d_in[1];
    const int*   e_false = (const int*)  d_in[2];
    const float* z       = (const float*)d_in[3];
    const float* W2      = (const float*)d_in[4];
    const float* W3      = (const float*)d_in[5];
    float* out = (float*)d_out;

    const int E_true  = in_sizes[1] / 2;
    const int E_total = E_true + in_sizes[2] / 2;

    int sm_count = 148;
    cudaDeviceGetAttribute(&sm_count, cudaDevAttrMultiProcessorCount, 0);

    convert_kernel<<<sm_count * 8, 256>>>(z, W2, W3);

    int blocks_per_sm = 3;
    cudaOccupancyMaxActiveBlocksPerMultiprocessor(&blocks_per_sm, neumf_kernel, 256, 0);
    if (blocks_per_sm < 1) blocks_per_sm = 1;

    neumf_kernel<<<sm_count * blocks_per_sm, 256>>>(e_true, e_false, out,
                                                    E_true, E_total);
}